// round 12
// baseline (speedup 1.0000x reference)
#include <cuda_runtime.h>

// NeuralODE: z' = conv1d(tanh(conv1d(z,W1,b1)),W2,b2), SSP-RK3, 20 steps,
// periodic ghost-cell refresh (IGST=10) after each substage (applied lazily via pmap).
//
// R5 (theory: LDS-slot bound, 2.45 slots/FMA, L1 pipe 55.6%):
//  - u tile transposed [pos][4ch]: conv1 window = 6 x LDS.128 per POSITION PAIR
//  - W1 permuted in smem to [c][k*4+ci]; weights loaded once per 2 positions
//  - full hidden tile in smem (64x133) -> no chunk loop, 2 barriers/stage (was 4)
//  - phase2: (position-pair, 16ch quarter) threads, quarters in-warp -> SHFL reduce
//  - divide/clamp-free tanh: 1 - 2/(e^{2x}+1)
//  - row pitch 133 (odd) keeps smem conflicts <=2-way
// (R12 resubmission: R5..R11 never ran — GPU acquisition timeouts, no measurement.)

#define LL    2048
#define GH    10
#define NCHN  4
#define HIDC  64
#define KSZ   5
#define MB    32
#define TL    128
#define NT    256
#define HW    (TL + 4)      // 132 hidden positions incl conv2 halo
#define HWP   133           // odd pitch: <=2-way smem conflicts
#define UW    (TL + 8)      // 136 input positions incl conv1+conv2 halo
#define SZ    (MB * NCHN * LL)
#define NSTEPS 20

__device__ float g_K1[SZ];
__device__ float g_K2[SZ];
__device__ float g_ZA[SZ];
__device__ float g_ZB[SZ];

__device__ __forceinline__ int pmap(int j) {
    // bdry(u)[j] = u[pmap(j)]
    if (j < GH)       return j + (LL - 2 * GH);
    if (j >= LL - GH) return j - (LL - 2 * GH);
    return j;
}

// exact-at-saturation tanh: no clamp needed (e->inf => 1, e->0 => -1)
__device__ __forceinline__ float tanh_fast(float x) {
    float e = __expf(x + x);
    return 1.0f - __fdividef(2.0f, e + 1.0f);
}

// OUT = alpha*Zread + beta*Uread + gamma*f(U), f = conv2(tanh(conv1(U))),
// Uread/Zread apply pmap() iff umap/zmap.
__global__ __launch_bounds__(NT, 4) void stage_kernel(
    const float* __restrict__ U, const float* __restrict__ Z,
    float* __restrict__ OUT,
    const float* __restrict__ W1, const float* __restrict__ b1,
    const float* __restrict__ W2, const float* __restrict__ b2,
    float alpha, float beta, float gamma, int umap, int zmap)
{
    __shared__ float4 u4_s[UW];              // transposed input tile [pos][4ch], 2176B
    __shared__ float  hid_s[HIDC][HWP];      // hidden tile, 34048B
    __shared__ float  W1p_s[HIDC * 20];      // permuted [c][k*4+ci]
    __shared__ float  W2t_s[HIDC * 20];      // [c][co*5+k]
    __shared__ float  b1_s[HIDC];
    __shared__ float  b2_s[NCHN];

    const int tid = threadIdx.x;
    const int t0  = blockIdx.x * TL;
    const int b   = blockIdx.y;

    // ---- stage weights into smem (W1 permuted, W2 transposed) ----
    for (int i = tid; i < HIDC * 20; i += NT) {
        int c = i / 20, t = i - c * 20;
        int k = t >> 2, ci = t & 3;
        W1p_s[i] = W1[c * 20 + ci * KSZ + k];
        int co = t / 5, kk = t - co * 5;
        W2t_s[i] = W2[(co * HIDC + c) * KSZ + kk];
    }
    if (tid < HIDC) b1_s[tid] = b1[tid];
    if (tid < NCHN) b2_s[tid] = b2[tid];

    const float* Ub = U + b * (NCHN * LL);

    // ---- u tile transposed [pos][ci]; zero outside [0,L); pmap if bdry'd ----
    for (int i = tid; i < UW * 4; i += NT) {
        int s  = i >> 2, ci = i & 3;
        int j  = t0 - 4 + s;
        float v = 0.0f;
        if (j >= 0 && j < LL) v = Ub[ci * LL + (umap ? pmap(j) : j)];
        ((float*)u4_s)[s * 4 + ci] = v;
    }
    __syncthreads();

    // ---- phase 1: hid[c][q] = tanh(conv1), position-PAIRS, 4ch per thread ----
    {
        const int cg = tid >> 4;        // 0..15 -> channels cg*4 .. cg*4+3
        const int ts = tid & 15;
        const int c0 = cg * 4;

        #pragma unroll
        for (int i = 0; i < 5; i++) {
            const int q = 2 * ts + 32 * i;       // even pair start
            if (q >= HW) break;                  // q<=130, pair (q,q+1) valid

            float u6[24];                        // overlapping windows of q and q+1
            #pragma unroll
            for (int k = 0; k < 6; k++) {
                float4 t4 = u4_s[q + k];
                u6[k * 4 + 0] = t4.x; u6[k * 4 + 1] = t4.y;
                u6[k * 4 + 2] = t4.z; u6[k * 4 + 3] = t4.w;
            }

            const int  gq0 = t0 - 2 + q;
            const bool v0  = (gq0 >= 0) && (gq0 < LL);
            const bool v1  = (gq0 + 1 >= 0) && (gq0 + 1 < LL);

            #pragma unroll
            for (int j = 0; j < 4; j++) {
                const int c = c0 + j;
                const float4* w4 = (const float4*)&W1p_s[c * 20];
                float wq[20];
                #pragma unroll
                for (int v = 0; v < 5; v++) {
                    float4 t4 = w4[v];
                    wq[v * 4 + 0] = t4.x; wq[v * 4 + 1] = t4.y;
                    wq[v * 4 + 2] = t4.z; wq[v * 4 + 3] = t4.w;
                }
                float a0 = b1_s[c], a1 = a0;
                #pragma unroll
                for (int t = 0; t < 20; t++) {
                    a0 = fmaf(wq[t], u6[t], a0);
                    a1 = fmaf(wq[t], u6[t + 4], a1);
                }
                hid_s[c][q]     = v0 ? tanh_fast(a0) : 0.0f;
                hid_s[c][q + 1] = v1 ? tanh_fast(a1) : 0.0f;
            }
        }
    }
    __syncthreads();

    // ---- phase 2: conv2 + combine; thread = (position pair, 16ch quarter) ----
    {
        const int qq = tid & 3;          // quarter (in-warp for SHFL reduce)
        const int pp = tid >> 2;         // 0..63 -> positions 2pp, 2pp+1
        const int p0 = 2 * pp;

        float accA[NCHN] = {0.f, 0.f, 0.f, 0.f};
        float accB[NCHN] = {0.f, 0.f, 0.f, 0.f};
        const int cbeg = qq * 16;

        #pragma unroll 4
        for (int it = 0; it < 16; it++) {
            const int c = cbeg + it;
            float hf[6];
            #pragma unroll
            for (int k = 0; k < 6; k++) hf[k] = hid_s[c][p0 + k];

            const float4* w4 = (const float4*)&W2t_s[c * 20];
            float wf[20];
            #pragma unroll
            for (int v = 0; v < 5; v++) {
                float4 t4 = w4[v];
                wf[v * 4 + 0] = t4.x; wf[v * 4 + 1] = t4.y;
                wf[v * 4 + 2] = t4.z; wf[v * 4 + 3] = t4.w;
            }
            #pragma unroll
            for (int co = 0; co < NCHN; co++)
                #pragma unroll
                for (int k = 0; k < KSZ; k++) {
                    accA[co] = fmaf(wf[co * 5 + k], hf[k],     accA[co]);
                    accB[co] = fmaf(wf[co * 5 + k], hf[k + 1], accB[co]);
                }
        }

        // reduce across the 4 quarters (lanes differing in bits 0,1)
        #pragma unroll
        for (int co = 0; co < NCHN; co++) {
            accA[co] += __shfl_xor_sync(0xffffffff, accA[co], 1);
            accA[co] += __shfl_xor_sync(0xffffffff, accA[co], 2);
            accB[co] += __shfl_xor_sync(0xffffffff, accB[co], 1);
            accB[co] += __shfl_xor_sync(0xffffffff, accB[co], 2);
        }

        if (qq == 0) {
            const int go0 = t0 + p0;
            // pmap preserves even-pair contiguity -> float2 loads/stores are safe
            const int ju = umap ? pmap(go0) : go0;
            const int jz = zmap ? pmap(go0) : go0;
            const float* Zb = Z + b * (NCHN * LL);
            float* Ob = OUT + b * (NCHN * LL);
            #pragma unroll
            for (int co = 0; co < NCHN; co++) {
                float2 z2 = *(const float2*)&Zb[co * LL + jz];
                float2 u2 = *(const float2*)&Ub[co * LL + ju];
                float fa = accA[co] + b2_s[co];
                float fb = accB[co] + b2_s[co];
                float2 o;
                o.x = alpha * z2.x + beta * u2.x + gamma * fa;
                o.y = alpha * z2.y + beta * u2.y + gamma * fb;
                *(float2*)&Ob[co * LL + go0] = o;
            }
        }
    }
}

// Final output = bdry(Z_raw)
__global__ void bdry_copy(const float* __restrict__ Zin, float* __restrict__ out)
{
    int i = blockIdx.x * blockDim.x + threadIdx.x;
    if (i >= SZ) return;
    int row = i / LL;
    int j   = i - row * LL;
    out[i] = Zin[row * LL + pmap(j)];
}

extern "C" void kernel_launch(void* const* d_in, const int* in_sizes, int n_in,
                              void* d_out, int out_size)
{
    const float* z0 = (const float*)d_in[0];
    const float* W1 = (const float*)d_in[1];
    const float* b1 = (const float*)d_in[2];
    const float* W2 = (const float*)d_in[3];
    const float* b2 = (const float*)d_in[4];
    // t1_t0 == 1 fixed by setup_inputs: n_steps = 20, h = 0.05

    float *K1, *K2, *ZA, *ZB;
    cudaGetSymbolAddress((void**)&K1, g_K1);
    cudaGetSymbolAddress((void**)&K2, g_K2);
    cudaGetSymbolAddress((void**)&ZA, g_ZA);
    cudaGetSymbolAddress((void**)&ZB, g_ZB);

    const float h = 1.0f / (float)NSTEPS;
    dim3 grid(LL / TL, MB);

    const float* Zc = z0;
    int zm = 0;

    for (int s = 0; s < NSTEPS; s++) {
        // k1 = bdry(z + h f(z))
        stage_kernel<<<grid, NT>>>(Zc, Zc, K1, W1, b1, W2, b2,
                                   1.0f, 0.0f, h, zm, zm);
        // k2 = bdry(0.75 z + 0.25 k1 + 0.25 h f(k1))
        stage_kernel<<<grid, NT>>>(K1, Zc, K2, W1, b1, W2, b2,
                                   0.75f, 0.25f, 0.25f * h, 1, zm);
        // z_new = bdry(z/3 + 2/3 k2 + 2h/3 f(k2))
        float* Zn = (s % 2 == 0) ? ZA : ZB;
        stage_kernel<<<grid, NT>>>(K2, Zc, Zn, W1, b1, W2, b2,
                                   1.0f / 3.0f, 2.0f / 3.0f, 2.0f * h / 3.0f, 1, zm);
        Zc = Zn;
        zm = 1;
    }

    bdry_copy<<<(SZ + 255) / 256, 256>>>(Zc, (float*)d_out);
}

// round 13
// speedup vs baseline: 1.0126x; 1.0126x over previous
#include <cuda_runtime.h>

// NeuralODE: z' = conv1d(tanh(conv1d(z,W1,b1)),W2,b2), SSP-RK3, 20 steps,
// periodic ghost-cell refresh (IGST=10) after each substage (applied lazily via pmap).
//
// R6 (post-mortem of R5 @4054us: register SPILLS -> L2 30%, local mem traffic.
//     u6[24]+wq[20] live > 64-reg cap. Fix: stream weights, never buffer them):
//  - weights consumed float4-at-a-time (load t4 -> 8 FMAs -> dead). Peak live:
//    phase1 ~34 regs, phase2 ~20 regs. No spills at launch_bounds(256,4).
//  - everything else identical to R5: [pos][4ch] u tile (6xLDS.128/pair),
//    permuted W1, resident 64x133 hidden tile, 2 barriers/stage, SHFL reduce,
//    6-slot saturation-exact tanh.

#define LL    2048
#define GH    10
#define NCHN  4
#define HIDC  64
#define KSZ   5
#define MB    32
#define TL    128
#define NT    256
#define HW    (TL + 4)      // 132 hidden positions incl conv2 halo
#define HWP   133           // odd pitch: <=2-way smem conflicts
#define UW    (TL + 8)      // 136 input positions incl conv1+conv2 halo
#define SZ    (MB * NCHN * LL)
#define NSTEPS 20

__device__ float g_K1[SZ];
__device__ float g_K2[SZ];
__device__ float g_ZA[SZ];
__device__ float g_ZB[SZ];

__device__ __forceinline__ int pmap(int j) {
    // bdry(u)[j] = u[pmap(j)]
    if (j < GH)       return j + (LL - 2 * GH);
    if (j >= LL - GH) return j - (LL - 2 * GH);
    return j;
}

// exact-at-saturation tanh: no clamp needed (e->inf => 1, e->0 => -1)
__device__ __forceinline__ float tanh_fast(float x) {
    float e = __expf(x + x);
    return 1.0f - __fdividef(2.0f, e + 1.0f);
}

// OUT = alpha*Zread + beta*Uread + gamma*f(U), f = conv2(tanh(conv1(U))),
// Uread/Zread apply pmap() iff umap/zmap.
__global__ __launch_bounds__(NT, 4) void stage_kernel(
    const float* __restrict__ U, const float* __restrict__ Z,
    float* __restrict__ OUT,
    const float* __restrict__ W1, const float* __restrict__ b1,
    const float* __restrict__ W2, const float* __restrict__ b2,
    float alpha, float beta, float gamma, int umap, int zmap)
{
    __shared__ float4 u4_s[UW];              // transposed input tile [pos][4ch], 2176B
    __shared__ float  hid_s[HIDC][HWP];      // hidden tile, 34048B
    __shared__ float  W1p_s[HIDC * 20];      // permuted [c][k*4+ci]
    __shared__ float  W2t_s[HIDC * 20];      // [c][co*5+k]
    __shared__ float  b1_s[HIDC];
    __shared__ float  b2_s[NCHN];

    const int tid = threadIdx.x;
    const int t0  = blockIdx.x * TL;
    const int b   = blockIdx.y;

    // ---- stage weights into smem (W1 permuted, W2 transposed) ----
    for (int i = tid; i < HIDC * 20; i += NT) {
        int c = i / 20, t = i - c * 20;
        int k = t >> 2, ci = t & 3;
        W1p_s[i] = W1[c * 20 + ci * KSZ + k];
        int co = t / 5, kk = t - co * 5;
        W2t_s[i] = W2[(co * HIDC + c) * KSZ + kk];
    }
    if (tid < HIDC) b1_s[tid] = b1[tid];
    if (tid < NCHN) b2_s[tid] = b2[tid];

    const float* Ub = U + b * (NCHN * LL);

    // ---- u tile transposed [pos][ci]; zero outside [0,L); pmap if bdry'd ----
    for (int i = tid; i < UW * 4; i += NT) {
        int s  = i >> 2, ci = i & 3;
        int j  = t0 - 4 + s;
        float v = 0.0f;
        if (j >= 0 && j < LL) v = Ub[ci * LL + (umap ? pmap(j) : j)];
        ((float*)u4_s)[s * 4 + ci] = v;
    }
    __syncthreads();

    // ---- phase 1: hid[c][q] = tanh(conv1), position-PAIRS, 4ch per thread ----
    {
        const int cg = tid >> 4;        // 0..15 -> channels cg*4 .. cg*4+3
        const int ts = tid & 15;
        const int c0 = cg * 4;

        #pragma unroll
        for (int i = 0; i < 5; i++) {
            const int q = 2 * ts + 32 * i;       // even pair start
            if (q >= HW) break;                  // q<=130, pair (q,q+1) valid

            float u6[24];                        // overlapping windows of q and q+1
            #pragma unroll
            for (int k = 0; k < 6; k++) {
                float4 t4 = u4_s[q + k];
                u6[k * 4 + 0] = t4.x; u6[k * 4 + 1] = t4.y;
                u6[k * 4 + 2] = t4.z; u6[k * 4 + 3] = t4.w;
            }

            const int  gq0 = t0 - 2 + q;
            const bool v0  = (gq0 >= 0) && (gq0 < LL);
            const bool v1  = (gq0 + 1 >= 0) && (gq0 + 1 < LL);

            #pragma unroll
            for (int j = 0; j < 4; j++) {
                const int c = c0 + j;
                const float4* w4 = (const float4*)&W1p_s[c * 20];
                float a0 = b1_s[c], a1 = a0;
                // stream weights: one float4 live at a time (no wq[20] buffer)
                #pragma unroll
                for (int v = 0; v < 5; v++) {
                    float4 t4 = w4[v];
                    float wv[4] = {t4.x, t4.y, t4.z, t4.w};
                    #pragma unroll
                    for (int e = 0; e < 4; e++) {
                        const int idx = v * 4 + e;
                        a0 = fmaf(wv[e], u6[idx],     a0);
                        a1 = fmaf(wv[e], u6[idx + 4], a1);
                    }
                }
                hid_s[c][q]     = v0 ? tanh_fast(a0) : 0.0f;
                hid_s[c][q + 1] = v1 ? tanh_fast(a1) : 0.0f;
            }
        }
    }
    __syncthreads();

    // ---- phase 2: conv2 + combine; thread = (position pair, 16ch quarter) ----
    {
        const int qq = tid & 3;          // quarter (in-warp for SHFL reduce)
        const int pp = tid >> 2;         // 0..63 -> positions 2pp, 2pp+1
        const int p0 = 2 * pp;

        float accA[NCHN] = {0.f, 0.f, 0.f, 0.f};
        float accB[NCHN] = {0.f, 0.f, 0.f, 0.f};
        const int cbeg = qq * 16;

        #pragma unroll 4
        for (int it = 0; it < 16; it++) {
            const int c = cbeg + it;
            float hf[6];
            #pragma unroll
            for (int k = 0; k < 6; k++) hf[k] = hid_s[c][p0 + k];

            const float4* w4 = (const float4*)&W2t_s[c * 20];
            // stream weights: one float4 live at a time (no wf[20] buffer);
            // idx = co*5+k constant-folds under full unroll
            #pragma unroll
            for (int v = 0; v < 5; v++) {
                float4 t4 = w4[v];
                float wv[4] = {t4.x, t4.y, t4.z, t4.w};
                #pragma unroll
                for (int e = 0; e < 4; e++) {
                    const int idx = v * 4 + e;
                    const int co  = idx / 5;
                    const int k   = idx - co * 5;
                    accA[co] = fmaf(wv[e], hf[k],     accA[co]);
                    accB[co] = fmaf(wv[e], hf[k + 1], accB[co]);
                }
            }
        }

        // reduce across the 4 quarters (lanes differing in bits 0,1)
        #pragma unroll
        for (int co = 0; co < NCHN; co++) {
            accA[co] += __shfl_xor_sync(0xffffffff, accA[co], 1);
            accA[co] += __shfl_xor_sync(0xffffffff, accA[co], 2);
            accB[co] += __shfl_xor_sync(0xffffffff, accB[co], 1);
            accB[co] += __shfl_xor_sync(0xffffffff, accB[co], 2);
        }

        if (qq == 0) {
            const int go0 = t0 + p0;
            // pmap preserves even-pair contiguity -> float2 loads/stores are safe
            const int ju = umap ? pmap(go0) : go0;
            const int jz = zmap ? pmap(go0) : go0;
            const float* Zb = Z + b * (NCHN * LL);
            float* Ob = OUT + b * (NCHN * LL);
            #pragma unroll
            for (int co = 0; co < NCHN; co++) {
                float2 z2 = *(const float2*)&Zb[co * LL + jz];
                float2 u2 = *(const float2*)&Ub[co * LL + ju];
                float fa = accA[co] + b2_s[co];
                float fb = accB[co] + b2_s[co];
                float2 o;
                o.x = alpha * z2.x + beta * u2.x + gamma * fa;
                o.y = alpha * z2.y + beta * u2.y + gamma * fb;
                *(float2*)&Ob[co * LL + go0] = o;
            }
        }
    }
}

// Final output = bdry(Z_raw)
__global__ void bdry_copy(const float* __restrict__ Zin, float* __restrict__ out)
{
    int i = blockIdx.x * blockDim.x + threadIdx.x;
    if (i >= SZ) return;
    int row = i / LL;
    int j   = i - row * LL;
    out[i] = Zin[row * LL + pmap(j)];
}

extern "C" void kernel_launch(void* const* d_in, const int* in_sizes, int n_in,
                              void* d_out, int out_size)
{
    const float* z0 = (const float*)d_in[0];
    const float* W1 = (const float*)d_in[1];
    const float* b1 = (const float*)d_in[2];
    const float* W2 = (const float*)d_in[3];
    const float* b2 = (const float*)d_in[4];
    // t1_t0 == 1 fixed by setup_inputs: n_steps = 20, h = 0.05

    float *K1, *K2, *ZA, *ZB;
    cudaGetSymbolAddress((void**)&K1, g_K1);
    cudaGetSymbolAddress((void**)&K2, g_K2);
    cudaGetSymbolAddress((void**)&ZA, g_ZA);
    cudaGetSymbolAddress((void**)&ZB, g_ZB);

    const float h = 1.0f / (float)NSTEPS;
    dim3 grid(LL / TL, MB);

    const float* Zc = z0;
    int zm = 0;

    for (int s = 0; s < NSTEPS; s++) {
        // k1 = bdry(z + h f(z))
        stage_kernel<<<grid, NT>>>(Zc, Zc, K1, W1, b1, W2, b2,
                                   1.0f, 0.0f, h, zm, zm);
        // k2 = bdry(0.75 z + 0.25 k1 + 0.25 h f(k1))
        stage_kernel<<<grid, NT>>>(K1, Zc, K2, W1, b1, W2, b2,
                                   0.75f, 0.25f, 0.25f * h, 1, zm);
        // z_new = bdry(z/3 + 2/3 k2 + 2h/3 f(k2))
        float* Zn = (s % 2 == 0) ? ZA : ZB;
        stage_kernel<<<grid, NT>>>(K2, Zc, Zn, W1, b1, W2, b2,
                                   1.0f / 3.0f, 2.0f / 3.0f, 2.0f * h / 3.0f, 1, zm);
        Zc = Zn;
        zm = 1;
    }

    bdry_copy<<<(SZ + 255) / 256, 256>>>(Zc, (float*)d_out);
}

// round 16
// speedup vs baseline: 1.8626x; 1.8393x over previous
#include <cuda_runtime.h>

// NeuralODE: z' = conv1d(tanh(conv1d(z,W1,b1)),W2,b2), SSP-RK3, 20 steps,
// periodic ghost-cell refresh (IGST=10) after each substage (applied lazily via pmap).
//
// R7 (post-mortem R5/R6 @~4000us: SPILLS from ptxas fully unrolling the phase-1
//     pair loop (5 live u6[24] buffers + hoisted LDS) against the 64-reg cap;
//     source-level weight streaming was a no-op because ptxas reschedules):
//  - #pragma unroll 1 on phase-1 pair loop  -> one iteration live (~35 regs)
//  - #pragma unroll 2 on phase-2 channel loop (was 4)
//  - __launch_bounds__(256,3) -> 85-reg cap; occ 37.5% vs 38.4% (smem-bound
//    anyway), spills structurally impossible
//  - data layout unchanged from R5: [pos][4ch] u tile (6xLDS.128/pair),
//    permuted W1, resident 64x133 hidden tile, 2 barriers/stage, SHFL reduce,
//    6-slot saturation-exact tanh
// (R16 resubmission: R7 never ran — GPU acquisition timeouts at R14/R15.)

#define LL    2048
#define GH    10
#define NCHN  4
#define HIDC  64
#define KSZ   5
#define MB    32
#define TL    128
#define NT    256
#define HW    (TL + 4)      // 132 hidden positions incl conv2 halo
#define HWP   133           // odd pitch: <=2-way smem conflicts
#define UW    (TL + 8)      // 136 input positions incl conv1+conv2 halo
#define SZ    (MB * NCHN * LL)
#define NSTEPS 20

__device__ float g_K1[SZ];
__device__ float g_K2[SZ];
__device__ float g_ZA[SZ];
__device__ float g_ZB[SZ];

__device__ __forceinline__ int pmap(int j) {
    // bdry(u)[j] = u[pmap(j)]
    if (j < GH)       return j + (LL - 2 * GH);
    if (j >= LL - GH) return j - (LL - 2 * GH);
    return j;
}

// exact-at-saturation tanh: no clamp needed (e->inf => 1, e->0 => -1)
__device__ __forceinline__ float tanh_fast(float x) {
    float e = __expf(x + x);
    return 1.0f - __fdividef(2.0f, e + 1.0f);
}

// OUT = alpha*Zread + beta*Uread + gamma*f(U), f = conv2(tanh(conv1(U))),
// Uread/Zread apply pmap() iff umap/zmap.
__global__ __launch_bounds__(NT, 3) void stage_kernel(
    const float* __restrict__ U, const float* __restrict__ Z,
    float* __restrict__ OUT,
    const float* __restrict__ W1, const float* __restrict__ b1,
    const float* __restrict__ W2, const float* __restrict__ b2,
    float alpha, float beta, float gamma, int umap, int zmap)
{
    __shared__ float4 u4_s[UW];              // transposed input tile [pos][4ch], 2176B
    __shared__ float  hid_s[HIDC][HWP];      // hidden tile, 34048B
    __shared__ float  W1p_s[HIDC * 20];      // permuted [c][k*4+ci]
    __shared__ float  W2t_s[HIDC * 20];      // [c][co*5+k]
    __shared__ float  b1_s[HIDC];
    __shared__ float  b2_s[NCHN];

    const int tid = threadIdx.x;
    const int t0  = blockIdx.x * TL;
    const int b   = blockIdx.y;

    // ---- stage weights into smem (W1 permuted, W2 transposed) ----
    for (int i = tid; i < HIDC * 20; i += NT) {
        int c = i / 20, t = i - c * 20;
        int k = t >> 2, ci = t & 3;
        W1p_s[i] = W1[c * 20 + ci * KSZ + k];
        int co = t / 5, kk = t - co * 5;
        W2t_s[i] = W2[(co * HIDC + c) * KSZ + kk];
    }
    if (tid < HIDC) b1_s[tid] = b1[tid];
    if (tid < NCHN) b2_s[tid] = b2[tid];

    const float* Ub = U + b * (NCHN * LL);

    // ---- u tile transposed [pos][ci]; zero outside [0,L); pmap if bdry'd ----
    for (int i = tid; i < UW * 4; i += NT) {
        int s  = i >> 2, ci = i & 3;
        int j  = t0 - 4 + s;
        float v = 0.0f;
        if (j >= 0 && j < LL) v = Ub[ci * LL + (umap ? pmap(j) : j)];
        ((float*)u4_s)[s * 4 + ci] = v;
    }
    __syncthreads();

    // ---- phase 1: hid[c][q] = tanh(conv1), position-PAIRS, 4ch per thread ----
    {
        const int cg = tid >> 4;        // 0..15 -> channels cg*4 .. cg*4+3
        const int ts = tid & 15;
        const int c0 = cg * 4;

        // NOT unrolled: one iteration's live set (~35 regs) at a time.
        #pragma unroll 1
        for (int i = 0; i < 5; i++) {
            const int q = 2 * ts + 32 * i;       // even pair start
            if (q >= HW) break;                  // q<=130, pair (q,q+1) valid

            float u6[24];                        // overlapping windows of q and q+1
            #pragma unroll
            for (int k = 0; k < 6; k++) {
                float4 t4 = u4_s[q + k];
                u6[k * 4 + 0] = t4.x; u6[k * 4 + 1] = t4.y;
                u6[k * 4 + 2] = t4.z; u6[k * 4 + 3] = t4.w;
            }

            const int  gq0 = t0 - 2 + q;
            const bool v0  = (gq0 >= 0) && (gq0 < LL);
            const bool v1  = (gq0 + 1 >= 0) && (gq0 + 1 < LL);

            #pragma unroll
            for (int j = 0; j < 4; j++) {
                const int c = c0 + j;
                const float4* w4 = (const float4*)&W1p_s[c * 20];
                float a0 = b1_s[c], a1 = a0;
                #pragma unroll
                for (int v = 0; v < 5; v++) {
                    float4 t4 = w4[v];
                    float wv[4] = {t4.x, t4.y, t4.z, t4.w};
                    #pragma unroll
                    for (int e = 0; e < 4; e++) {
                        const int idx = v * 4 + e;
                        a0 = fmaf(wv[e], u6[idx],     a0);
                        a1 = fmaf(wv[e], u6[idx + 4], a1);
                    }
                }
                hid_s[c][q]     = v0 ? tanh_fast(a0) : 0.0f;
                hid_s[c][q + 1] = v1 ? tanh_fast(a1) : 0.0f;
            }
        }
    }
    __syncthreads();

    // ---- phase 2: conv2 + combine; thread = (position pair, 16ch quarter) ----
    {
        const int qq = tid & 3;          // quarter (in-warp for SHFL reduce)
        const int pp = tid >> 2;         // 0..63 -> positions 2pp, 2pp+1
        const int p0 = 2 * pp;

        float accA[NCHN] = {0.f, 0.f, 0.f, 0.f};
        float accB[NCHN] = {0.f, 0.f, 0.f, 0.f};
        const int cbeg = qq * 16;

        // modest interleave: 2 iterations live (~30 regs incl. 8 accumulators)
        #pragma unroll 2
        for (int it = 0; it < 16; it++) {
            const int c = cbeg + it;
            float hf[6];
            #pragma unroll
            for (int k = 0; k < 6; k++) hf[k] = hid_s[c][p0 + k];

            const float4* w4 = (const float4*)&W2t_s[c * 20];
            #pragma unroll
            for (int v = 0; v < 5; v++) {
                float4 t4 = w4[v];
                float wv[4] = {t4.x, t4.y, t4.z, t4.w};
                #pragma unroll
                for (int e = 0; e < 4; e++) {
                    const int idx = v * 4 + e;
                    const int co  = idx / 5;
                    const int k   = idx - co * 5;
                    accA[co] = fmaf(wv[e], hf[k],     accA[co]);
                    accB[co] = fmaf(wv[e], hf[k + 1], accB[co]);
                }
            }
        }

        // reduce across the 4 quarters (lanes differing in bits 0,1)
        #pragma unroll
        for (int co = 0; co < NCHN; co++) {
            accA[co] += __shfl_xor_sync(0xffffffff, accA[co], 1);
            accA[co] += __shfl_xor_sync(0xffffffff, accA[co], 2);
            accB[co] += __shfl_xor_sync(0xffffffff, accB[co], 1);
            accB[co] += __shfl_xor_sync(0xffffffff, accB[co], 2);
        }

        if (qq == 0) {
            const int go0 = t0 + p0;
            // pmap preserves even-pair contiguity -> float2 loads/stores are safe
            const int ju = umap ? pmap(go0) : go0;
            const int jz = zmap ? pmap(go0) : go0;
            const float* Zb = Z + b * (NCHN * LL);
            float* Ob = OUT + b * (NCHN * LL);
            #pragma unroll
            for (int co = 0; co < NCHN; co++) {
                float2 z2 = *(const float2*)&Zb[co * LL + jz];
                float2 u2 = *(const float2*)&Ub[co * LL + ju];
                float fa = accA[co] + b2_s[co];
                float fb = accB[co] + b2_s[co];
                float2 o;
                o.x = alpha * z2.x + beta * u2.x + gamma * fa;
                o.y = alpha * z2.y + beta * u2.y + gamma * fb;
                *(float2*)&Ob[co * LL + go0] = o;
            }
        }
    }
}

// Final output = bdry(Z_raw)
__global__ void bdry_copy(const float* __restrict__ Zin, float* __restrict__ out)
{
    int i = blockIdx.x * blockDim.x + threadIdx.x;
    if (i >= SZ) return;
    int row = i / LL;
    int j   = i - row * LL;
    out[i] = Zin[row * LL + pmap(j)];
}

extern "C" void kernel_launch(void* const* d_in, const int* in_sizes, int n_in,
                              void* d_out, int out_size)
{
    const float* z0 = (const float*)d_in[0];
    const float* W1 = (const float*)d_in[1];
    const float* b1 = (const float*)d_in[2];
    const float* W2 = (const float*)d_in[3];
    const float* b2 = (const float*)d_in[4];
    // t1_t0 == 1 fixed by setup_inputs: n_steps = 20, h = 0.05

    float *K1, *K2, *ZA, *ZB;
    cudaGetSymbolAddress((void**)&K1, g_K1);
    cudaGetSymbolAddress((void**)&K2, g_K2);
    cudaGetSymbolAddress((void**)&ZA, g_ZA);
    cudaGetSymbolAddress((void**)&ZB, g_ZB);

    const float h = 1.0f / (float)NSTEPS;
    dim3 grid(LL / TL, MB);

    const float* Zc = z0;
    int zm = 0;

    for (int s = 0; s < NSTEPS; s++) {
        // k1 = bdry(z + h f(z))
        stage_kernel<<<grid, NT>>>(Zc, Zc, K1, W1, b1, W2, b2,
                                   1.0f, 0.0f, h, zm, zm);
        // k2 = bdry(0.75 z + 0.25 k1 + 0.25 h f(k1))
        stage_kernel<<<grid, NT>>>(K1, Zc, K2, W1, b1, W2, b2,
                                   0.75f, 0.25f, 0.25f * h, 1, zm);
        // z_new = bdry(z/3 + 2/3 k2 + 2h/3 f(k2))
        float* Zn = (s % 2 == 0) ? ZA : ZB;
        stage_kernel<<<grid, NT>>>(K2, Zc, Zn, W1, b1, W2, b2,
                                   1.0f / 3.0f, 2.0f / 3.0f, 2.0f * h / 3.0f, 1, zm);
        Zc = Zn;
        zm = 1;
    }

    bdry_copy<<<(SZ + 255) / 256, 256>>>(Zc, (float*)d_out);
}